// round 5
// baseline (speedup 1.0000x reference)
#include <cuda_runtime.h>

#define N_NODES 50000
#define N_EDGES 800000
#define DH 64
#define NG 64

// ---------------- device scratch (no allocations allowed) -----------------
__device__ float  g_dinv[N_NODES];
__device__ int    g_degi[N_NODES];          // in-degree (no self loop)
__device__ int    g_off[N_NODES + 1];       // CSR offsets by destination
__device__ int    g_cur[N_NODES];           // scatter cursor
__device__ int2   g_edge[N_EDGES];          // (src, weight-as-int) in CSR order
__device__ float4 g_t[N_NODES * 16];        // in @ W
__device__ float4 g_h[N_NODES * 16];        // layer output
__device__ int    g_start[NG + 1];          // graph boundaries in sorted batch

__device__ __forceinline__ float4 f4add(float4 a, float4 b) {
    return make_float4(a.x + b.x, a.y + b.y, a.z + b.z, a.w + b.w);
}
__device__ __forceinline__ float4 f4fma(float s, float4 v, float4 a) {
    return make_float4(fmaf(s, v.x, a.x), fmaf(s, v.y, a.y),
                       fmaf(s, v.z, a.z), fmaf(s, v.w, a.w));
}

// ---------------- prep ----------------
__global__ void clear_kernel() {
    int i = blockIdx.x * blockDim.x + threadIdx.x;
    if (i < N_NODES) g_degi[i] = 0;
}

__global__ void deg_kernel(const int* __restrict__ col) {
    int e = blockIdx.x * blockDim.x + threadIdx.x;
    if (e < N_EDGES) {
        int c = col[e];
        if (c >= 0 && c < N_NODES) atomicAdd(&g_degi[c], 1);
    }
}

__global__ void dinv_kernel() {
    int i = blockIdx.x * blockDim.x + threadIdx.x;
    if (i < N_NODES) g_dinv[i] = rsqrtf((float)g_degi[i] + 1.0f);  // +1 self loop
}

// single-block scan over degree counts -> CSR offsets + cursor
__global__ void scan_kernel() {
    __shared__ int s[1024];
    const int C = (N_NODES + 1023) / 1024;  // 49
    int t = threadIdx.x;
    int base = t * C;
    int sum = 0;
    for (int k = 0; k < C; k++) {
        int i = base + k;
        if (i < N_NODES) sum += g_degi[i];
    }
    s[t] = sum;
    __syncthreads();
    for (int d = 1; d < 1024; d <<= 1) {
        int v = (t >= d) ? s[t - d] : 0;
        __syncthreads();
        s[t] += v;
        __syncthreads();
    }
    int run = s[t] - sum;  // exclusive prefix of this chunk
    for (int k = 0; k < C; k++) {
        int i = base + k;
        if (i < N_NODES) {
            g_off[i] = run;
            g_cur[i] = run;
            run += g_degi[i];
        }
    }
    if (t == 1023) g_off[N_NODES] = s[1023];
}

__global__ void scatter_kernel(const int* __restrict__ ei) {
    int e = blockIdx.x * blockDim.x + threadIdx.x;
    if (e >= N_EDGES) return;
    int r = ei[e];
    int c = ei[N_EDGES + e];
    if (r < 0 || r >= N_NODES || c < 0 || c >= N_NODES) return;
    int pos = atomicAdd(&g_cur[c], 1);
    float w = g_dinv[r] * g_dinv[c];
    g_edge[pos] = make_int2(r, __float_as_int(w));
}

// ---------------- GEMM: t = in @ W  (N x 64) @ (64 x 64) ------------------
// use_h != 0 -> read input rows from g_h (previous layer output)
__global__ void gemm_kernel(const float* __restrict__ in,
                            const float* __restrict__ W, int use_h) {
    __shared__ float4 Ws[DH * 16];  // 16 KB
    const float4* W4 = (const float4*)W;
    for (int i = threadIdx.x; i < DH * 16; i += blockDim.x) Ws[i] = W4[i];
    __syncthreads();

    int tid  = blockIdx.x * blockDim.x + threadIdx.x;
    int node = tid >> 4;
    int g    = tid & 15;
    if (node >= N_NODES) return;

    const float4* xr4 = use_h ? &g_h[node * 16] : (const float4*)(in + node * DH);
    float4 acc = make_float4(0.f, 0.f, 0.f, 0.f);
#pragma unroll
    for (int k4 = 0; k4 < DH / 4; k4++) {
        float4 xv = xr4[k4];
#pragma unroll
        for (int s = 0; s < 4; s++) {
            float xk = (s == 0) ? xv.x : (s == 1) ? xv.y : (s == 2) ? xv.z : xv.w;
            acc = f4fma(xk, Ws[(k4 * 4 + s) * 16 + g], acc);
        }
    }
    g_t[node * 16 + g] = acc;
}

// ---------------- fused aggregate: h = relu(csr_sum + selfloop + bias) ----
__global__ void agg_kernel(const float* __restrict__ bias) {
    int tid  = blockIdx.x * blockDim.x + threadIdx.x;
    int node = tid >> 4;
    int f    = tid & 15;
    if (node >= N_NODES) return;

    int beg = g_off[node];
    int end = g_off[node + 1];
    float di = g_dinv[node];
    float4 tv = g_t[node * 16 + f];
    float s = di * di;
    float4 acc = make_float4(tv.x * s, tv.y * s, tv.z * s, tv.w * s);

    int j = beg;
    for (; j + 1 < end; j += 2) {
        int2 e0 = g_edge[j];
        int2 e1 = g_edge[j + 1];
        float4 v0 = g_t[e0.x * 16 + f];
        float4 v1 = g_t[e1.x * 16 + f];
        acc = f4fma(__int_as_float(e0.y), v0, acc);
        acc = f4fma(__int_as_float(e1.y), v1, acc);
    }
    if (j < end) {
        int2 e0 = g_edge[j];
        acc = f4fma(__int_as_float(e0.y), g_t[e0.x * 16 + f], acc);
    }

    float4 b = ((const float4*)bias)[f];
    float4 r;
    r.x = fmaxf(acc.x + b.x, 0.f);
    r.y = fmaxf(acc.y + b.y, 0.f);
    r.z = fmaxf(acc.z + b.z, 0.f);
    r.w = fmaxf(acc.w + b.w, 0.f);
    g_h[node * 16 + f] = r;
}

// ---------------- pooling (batch sorted: contiguous per-graph ranges) -----
__global__ void bounds_kernel(const int* __restrict__ batch) {
    int i = blockIdx.x * blockDim.x + threadIdx.x;
    if (i >= N_NODES) return;
    int b  = batch[i];
    int bp = (i == 0) ? -1 : batch[i - 1];
    if (b < 0) b = 0;
    if (b >= NG) b = NG - 1;
    if (bp < -1) bp = -1;
    if (bp >= NG) bp = NG - 1;
    for (int g = bp + 1; g <= b; g++) g_start[g] = i;
    if (i == N_NODES - 1)
        for (int g = b + 1; g <= NG; g++) g_start[g] = N_NODES;
}

__global__ void pool_kernel(float* __restrict__ out) {
    __shared__ float4 sm[256];
    int g  = blockIdx.x;           // one block per graph
    int t  = threadIdx.x;
    int f  = t & 15;               // feature float4 index
    int r0 = t >> 4;               // row group 0..15
    int beg = g_start[g];
    int end = g_start[g + 1];

    float4 acc = make_float4(0.f, 0.f, 0.f, 0.f);
    for (int r = beg + r0; r < end; r += 16) acc = f4add(acc, g_h[r * 16 + f]);
    sm[t] = acc;
    __syncthreads();
#pragma unroll
    for (int s = 8; s > 0; s >>= 1) {
        if (r0 < s) sm[t] = f4add(sm[t], sm[t + s * 16]);
        __syncthreads();
    }
    if (r0 == 0) {
        float inv = 1.0f / fmaxf((float)(end - beg), 1.0f);
        float4 v = sm[f];
        v.x *= inv; v.y *= inv; v.z *= inv; v.w *= inv;
        ((float4*)out)[g * 16 + f] = v;
    }
}

// ---------------- launch: bind inputs BY ELEMENT COUNT --------------------
extern "C" void kernel_launch(void* const* d_in, const int* in_sizes, int n_in,
                              void* d_out, int out_size) {
    const float* x     = 0;
    const int*   ei    = 0;
    const int*   batch = 0;
    const float* W[3] = {0, 0, 0};
    const float* B[3] = {0, 0, 0};
    int nw = 0, nb = 0;

    for (int i = 0; i < n_in; i++) {
        int sz = in_sizes[i];
        if      (sz == N_NODES * DH)  x     = (const float*)d_in[i];
        else if (sz == 2 * N_EDGES)   ei    = (const int*)d_in[i];
        else if (sz == N_NODES)       batch = (const int*)d_in[i];
        else if (sz == DH * DH) { if (nw < 3) W[nw++] = (const float*)d_in[i]; }
        else if (sz == DH)      { if (nb < 3) B[nb++] = (const float*)d_in[i]; }
    }
    if (!x || !ei || !batch || nw != 3 || nb != 3) return;  // binding failed

    float* out = (float*)d_out;

    const int TB = 256;
    const int gE   = (N_EDGES + TB - 1) / TB;       // 3125
    const int gN   = (N_NODES + TB - 1) / TB;       // 196
    const int gN16 = (N_NODES * 16 + TB - 1) / TB;  // 3125

    // ---- CSR build + norms (once) ----
    clear_kernel<<<gN, TB>>>();
    deg_kernel<<<gE, TB>>>(ei + N_EDGES);
    dinv_kernel<<<gN, TB>>>();
    scan_kernel<<<1, 1024>>>();
    scatter_kernel<<<gE, TB>>>(ei);
    bounds_kernel<<<gN, TB>>>(batch);

    // ---- 3 GCN layers ----
    for (int l = 0; l < 3; l++) {
        gemm_kernel<<<gN16, TB>>>(x, W[l], l > 0);
        agg_kernel<<<gN16, TB>>>(B[l]);
    }

    // ---- global mean pool ----
    pool_kernel<<<NG, 256>>>(out);
}

// round 6
// speedup vs baseline: 1.3704x; 1.3704x over previous
#include <cuda_runtime.h>

#define N_NODES 50000
#define N_EDGES 800000
#define DH 64
#define NG 64

#define SCAN_B 512
#define SCAN_NBLK ((N_NODES + SCAN_B - 1) / SCAN_B)   // 98

// ---------------- device scratch (no allocations allowed) -----------------
__device__ float  g_dinv[N_NODES];
__device__ int    g_degi[N_NODES];          // in-degree (no self loop)
__device__ int    g_off[N_NODES + 1];       // CSR offsets by destination
__device__ int    g_cur[N_NODES];           // scatter cursor
__device__ int    g_bsum[SCAN_NBLK];        // per-block sums
__device__ int    g_bpre[SCAN_NBLK];        // per-block exclusive prefixes
__device__ int2   g_edge[N_EDGES];          // (src, weight-as-int) in CSR order
__device__ float4 g_t[N_NODES * 16];        // in @ W
__device__ float4 g_h[N_NODES * 16];        // layer output
__device__ int    g_start[NG + 1];          // graph boundaries in sorted batch

__device__ __forceinline__ float4 f4add(float4 a, float4 b) {
    return make_float4(a.x + b.x, a.y + b.y, a.z + b.z, a.w + b.w);
}
__device__ __forceinline__ float4 f4fma(float s, float4 v, float4 a) {
    return make_float4(fmaf(s, v.x, a.x), fmaf(s, v.y, a.y),
                       fmaf(s, v.z, a.z), fmaf(s, v.w, a.w));
}

// ---------------- prep ----------------
__global__ void clear_kernel() {
    int i = blockIdx.x * blockDim.x + threadIdx.x;
    if (i < N_NODES) g_degi[i] = 0;
}

__global__ void deg_kernel(const int* __restrict__ col) {
    int e = blockIdx.x * blockDim.x + threadIdx.x;
    if (e < N_EDGES) {
        int c = col[e];
        if (c >= 0 && c < N_NODES) atomicAdd(&g_degi[c], 1);
    }
}

// phase 1: per-block exclusive scan of degrees (+ fused dinv computation)
__global__ void scan1_kernel() {
    __shared__ int s[SCAN_B];
    int t = threadIdx.x;
    int i = blockIdx.x * SCAN_B + t;
    int v = (i < N_NODES) ? g_degi[i] : 0;
    if (i < N_NODES) g_dinv[i] = rsqrtf((float)v + 1.0f);  // +1 self loop
    s[t] = v;
    __syncthreads();
#pragma unroll
    for (int d = 1; d < SCAN_B; d <<= 1) {
        int u = (t >= d) ? s[t - d] : 0;
        __syncthreads();
        s[t] += u;
        __syncthreads();
    }
    if (i < N_NODES) g_off[i] = s[t] - v;           // local exclusive
    if (t == SCAN_B - 1) g_bsum[blockIdx.x] = s[t]; // block total
}

// phase 2: scan the 98 block sums (one tiny block)
__global__ void scan2_kernel() {
    __shared__ int s[128];
    int t = threadIdx.x;
    int v = (t < SCAN_NBLK) ? g_bsum[t] : 0;
    s[t] = v;
    __syncthreads();
#pragma unroll
    for (int d = 1; d < 128; d <<= 1) {
        int u = (t >= d) ? s[t - d] : 0;
        __syncthreads();
        s[t] += u;
        __syncthreads();
    }
    if (t < SCAN_NBLK) g_bpre[t] = s[t] - v;
    if (t == 127) g_off[N_NODES] = s[127];          // total edge count
}

// phase 3: add block prefixes, init cursor
__global__ void scan3_kernel() {
    int i = blockIdx.x * blockDim.x + threadIdx.x;
    if (i < N_NODES) {
        int off = g_off[i] + g_bpre[i / SCAN_B];
        g_off[i] = off;
        g_cur[i] = off;
    }
}

__global__ void scatter_kernel(const int* __restrict__ ei) {
    int e = blockIdx.x * blockDim.x + threadIdx.x;
    if (e >= N_EDGES) return;
    int r = ei[e];
    int c = ei[N_EDGES + e];
    if (r < 0 || r >= N_NODES || c < 0 || c >= N_NODES) return;
    int pos = atomicAdd(&g_cur[c], 1);
    float w = g_dinv[r] * g_dinv[c];
    g_edge[pos] = make_int2(r, __float_as_int(w));
}

// ---------------- GEMM: t = in @ W  (N x 64) @ (64 x 64) ------------------
__global__ void gemm_kernel(const float* __restrict__ in,
                            const float* __restrict__ W, int use_h) {
    __shared__ float4 Ws[DH * 16];  // 16 KB
    const float4* W4 = (const float4*)W;
    for (int i = threadIdx.x; i < DH * 16; i += blockDim.x) Ws[i] = W4[i];
    __syncthreads();

    int tid  = blockIdx.x * blockDim.x + threadIdx.x;
    int node = tid >> 4;
    int g    = tid & 15;
    if (node >= N_NODES) return;

    const float4* xr4 = use_h ? &g_h[node * 16] : (const float4*)(in + node * DH);
    float4 acc = make_float4(0.f, 0.f, 0.f, 0.f);
#pragma unroll
    for (int k4 = 0; k4 < DH / 4; k4++) {
        float4 xv = xr4[k4];
#pragma unroll
        for (int s = 0; s < 4; s++) {
            float xk = (s == 0) ? xv.x : (s == 1) ? xv.y : (s == 2) ? xv.z : xv.w;
            acc = f4fma(xk, Ws[(k4 * 4 + s) * 16 + g], acc);
        }
    }
    g_t[node * 16 + g] = acc;
}

// ---------------- fused aggregate: h = relu(csr_sum + selfloop + bias) ----
__global__ void agg_kernel(const float* __restrict__ bias) {
    int tid  = blockIdx.x * blockDim.x + threadIdx.x;
    int node = tid >> 4;
    int f    = tid & 15;
    if (node >= N_NODES) return;

    int beg = g_off[node];
    int end = g_off[node + 1];
    float di = g_dinv[node];
    float4 tv = g_t[node * 16 + f];
    float s = di * di;
    float4 acc = make_float4(tv.x * s, tv.y * s, tv.z * s, tv.w * s);

    int j = beg;
    for (; j + 1 < end; j += 2) {
        int2 e0 = g_edge[j];
        int2 e1 = g_edge[j + 1];
        float4 v0 = g_t[e0.x * 16 + f];
        float4 v1 = g_t[e1.x * 16 + f];
        acc = f4fma(__int_as_float(e0.y), v0, acc);
        acc = f4fma(__int_as_float(e1.y), v1, acc);
    }
    if (j < end) {
        int2 e0 = g_edge[j];
        acc = f4fma(__int_as_float(e0.y), g_t[e0.x * 16 + f], acc);
    }

    float4 b = ((const float4*)bias)[f];
    float4 r;
    r.x = fmaxf(acc.x + b.x, 0.f);
    r.y = fmaxf(acc.y + b.y, 0.f);
    r.z = fmaxf(acc.z + b.z, 0.f);
    r.w = fmaxf(acc.w + b.w, 0.f);
    g_h[node * 16 + f] = r;
}

// ---------------- pooling (batch sorted: contiguous per-graph ranges) -----
__global__ void bounds_kernel(const int* __restrict__ batch) {
    int i = blockIdx.x * blockDim.x + threadIdx.x;
    if (i >= N_NODES) return;
    int b  = batch[i];
    int bp = (i == 0) ? -1 : batch[i - 1];
    if (b < 0) b = 0;
    if (b >= NG) b = NG - 1;
    if (bp < -1) bp = -1;
    if (bp >= NG) bp = NG - 1;
    for (int g = bp + 1; g <= b; g++) g_start[g] = i;
    if (i == N_NODES - 1)
        for (int g = b + 1; g <= NG; g++) g_start[g] = N_NODES;
}

__global__ void pool_kernel(float* __restrict__ out) {
    __shared__ float4 sm[256];
    int g  = blockIdx.x;           // one block per graph
    int t  = threadIdx.x;
    int f  = t & 15;               // feature float4 index
    int r0 = t >> 4;               // row group 0..15
    int beg = g_start[g];
    int end = g_start[g + 1];

    float4 acc = make_float4(0.f, 0.f, 0.f, 0.f);
    for (int r = beg + r0; r < end; r += 16) acc = f4add(acc, g_h[r * 16 + f]);
    sm[t] = acc;
    __syncthreads();
#pragma unroll
    for (int s = 8; s > 0; s >>= 1) {
        if (r0 < s) sm[t] = f4add(sm[t], sm[t + s * 16]);
        __syncthreads();
    }
    if (r0 == 0) {
        float inv = 1.0f / fmaxf((float)(end - beg), 1.0f);
        float4 v = sm[f];
        v.x *= inv; v.y *= inv; v.z *= inv; v.w *= inv;
        ((float4*)out)[g * 16 + f] = v;
    }
}

// ---------------- launch: bind inputs BY ELEMENT COUNT --------------------
extern "C" void kernel_launch(void* const* d_in, const int* in_sizes, int n_in,
                              void* d_out, int out_size) {
    const float* x     = 0;
    const int*   ei    = 0;
    const int*   batch = 0;
    const float* W[3] = {0, 0, 0};
    const float* B[3] = {0, 0, 0};
    int nw = 0, nb = 0;

    for (int i = 0; i < n_in; i++) {
        int sz = in_sizes[i];
        if      (sz == N_NODES * DH)  x     = (const float*)d_in[i];
        else if (sz == 2 * N_EDGES)   ei    = (const int*)d_in[i];
        else if (sz == N_NODES)       batch = (const int*)d_in[i];
        else if (sz == DH * DH) { if (nw < 3) W[nw++] = (const float*)d_in[i]; }
        else if (sz == DH)      { if (nb < 3) B[nb++] = (const float*)d_in[i]; }
    }
    if (!x || !ei || !batch || nw != 3 || nb != 3) return;  // binding failed

    float* out = (float*)d_out;

    const int TB = 256;
    const int gE   = (N_EDGES + TB - 1) / TB;       // 3125
    const int gN   = (N_NODES + TB - 1) / TB;       // 196
    const int gN16 = (N_NODES * 16 + TB - 1) / TB;  // 3125

    // ---- CSR build + norms (once) ----
    clear_kernel<<<gN, TB>>>();
    deg_kernel<<<gE, TB>>>(ei + N_EDGES);
    scan1_kernel<<<SCAN_NBLK, SCAN_B>>>();
    scan2_kernel<<<1, 128>>>();
    scan3_kernel<<<gN, TB>>>();
    scatter_kernel<<<gE, TB>>>(ei);
    bounds_kernel<<<gN, TB>>>(batch);

    // ---- 3 GCN layers ----
    for (int l = 0; l < 3; l++) {
        gemm_kernel<<<gN16, TB>>>(x, W[l], l > 0);
        agg_kernel<<<gN16, TB>>>(B[l]);
    }

    // ---- global mean pool ----
    pool_kernel<<<NG, 256>>>(out);
}

// round 7
// speedup vs baseline: 1.8864x; 1.3766x over previous
#include <cuda_runtime.h>

#define N_NODES 50000
#define N_EDGES 800000
#define DH 64
#define NG 64

#define SCAN_B 512
#define SCAN_NBLK ((N_NODES + SCAN_B - 1) / SCAN_B)   // 98

// ---------------- device scratch ----------------
__device__ float  g_dinv[N_NODES];
__device__ int    g_degi[N_NODES];
__device__ int    g_off[N_NODES + 1];
__device__ int    g_cur[N_NODES];
__device__ int    g_bsum[SCAN_NBLK];
__device__ int2   g_edge[N_EDGES];
__device__ float4 g_t[N_NODES * 16];
__device__ float4 g_h[N_NODES * 16];
__device__ int    g_start[NG + 1];

__device__ __forceinline__ float4 f4add(float4 a, float4 b) {
    return make_float4(a.x + b.x, a.y + b.y, a.z + b.z, a.w + b.w);
}
__device__ __forceinline__ float4 f4fma(float s, float4 v, float4 a) {
    return make_float4(fmaf(s, v.x, a.x), fmaf(s, v.y, a.y),
                       fmaf(s, v.z, a.z), fmaf(s, v.w, a.w));
}

// packed f32x2 helpers (Blackwell dual-FP32 pipe; PTX-only)
__device__ __forceinline__ unsigned long long pk2(float a, float b) {
    unsigned long long r;
    asm("mov.b64 %0, {%1, %2};" : "=l"(r) : "f"(a), "f"(b));
    return r;
}
__device__ __forceinline__ void fma2(unsigned long long& d,
                                     unsigned long long a, unsigned long long b) {
    asm("fma.rn.f32x2 %0, %1, %2, %0;" : "+l"(d) : "l"(a), "l"(b));
}
__device__ __forceinline__ float2 upk2(unsigned long long v) {
    float2 f;
    asm("mov.b64 {%0, %1}, %2;" : "=f"(f.x), "=f"(f.y) : "l"(v));
    return f;
}

// ---------------- prep ----------------
__global__ void clear_kernel() {
    int i = blockIdx.x * blockDim.x + threadIdx.x;
    if (i < N_NODES) g_degi[i] = 0;
}

__global__ void deg_kernel(const int* __restrict__ col) {
    int e = blockIdx.x * blockDim.x + threadIdx.x;
    if (e < N_EDGES) {
        int c = col[e];
        if (c >= 0 && c < N_NODES) atomicAdd(&g_degi[c], 1);
    }
}

// phase 1: per-block exclusive scan of degrees (+ fused dinv)
__global__ void scan1_kernel() {
    __shared__ int s[SCAN_B];
    int t = threadIdx.x;
    int i = blockIdx.x * SCAN_B + t;
    int v = (i < N_NODES) ? g_degi[i] : 0;
    if (i < N_NODES) g_dinv[i] = rsqrtf((float)v + 1.0f);
    s[t] = v;
    __syncthreads();
#pragma unroll
    for (int d = 1; d < SCAN_B; d <<= 1) {
        int u = (t >= d) ? s[t - d] : 0;
        __syncthreads();
        s[t] += u;
        __syncthreads();
    }
    if (i < N_NODES) g_off[i] = s[t] - v;
    if (t == SCAN_B - 1) g_bsum[blockIdx.x] = s[t];
}

// phase 2+3 fused (+ graph bounds): every block redundantly scans the 98
// block sums in smem, then adds the prefix to its slice. Also computes
// g_start from sorted batch (independent node-indexed work).
__global__ void scan3_kernel(const int* __restrict__ batch) {
    __shared__ int s[128];
    int t = threadIdx.x;  // 256 threads
    if (t < 128) {
        int v = (t < SCAN_NBLK) ? g_bsum[t] : 0;
        s[t] = v;
    }
    __syncthreads();
#pragma unroll
    for (int d = 1; d < 128; d <<= 1) {
        int u = 0;
        if (t < 128 && t >= d) u = s[t - d];
        __syncthreads();
        if (t < 128) s[t] += u;
        __syncthreads();
    }
    int i = blockIdx.x * blockDim.x + t;
    if (i < N_NODES) {
        int blk = i / SCAN_B;
        int pre = s[blk] - g_bsum[blk];  // exclusive prefix of blk
        int off = g_off[i] + pre;
        g_off[i] = off;
        g_cur[i] = off;
        if (i == 0) g_off[N_NODES] = s[127];

        // graph boundaries
        int b  = batch[i];
        int bp = (i == 0) ? -1 : batch[i - 1];
        if (b < 0) b = 0;
        if (b >= NG) b = NG - 1;
        if (bp < -1) bp = -1;
        if (bp >= NG) bp = NG - 1;
        for (int g = bp + 1; g <= b; g++) g_start[g] = i;
        if (i == N_NODES - 1)
            for (int g = b + 1; g <= NG; g++) g_start[g] = N_NODES;
    }
}

__global__ void scatter_kernel(const int* __restrict__ ei) {
    int e = blockIdx.x * blockDim.x + threadIdx.x;
    if (e >= N_EDGES) return;
    int r = ei[e];
    int c = ei[N_EDGES + e];
    if (r < 0 || r >= N_NODES || c < 0 || c >= N_NODES) return;
    int pos = atomicAdd(&g_cur[c], 1);
    float w = g_dinv[r] * g_dinv[c];
    g_edge[pos] = make_int2(r, __float_as_int(w));
}

// ---------------- GEMM: t = in @ W ; 4 nodes/thread, f32x2 packed ---------
#define GEMM_B 256
__global__ void gemm_kernel(const float* __restrict__ in,
                            const float* __restrict__ W, int use_h) {
    __shared__ float4 Ws[DH * 16];  // 16 KB
    const float4* W4 = (const float4*)W;
    for (int i = threadIdx.x; i < DH * 16; i += GEMM_B) Ws[i] = W4[i];
    __syncthreads();

    int tid  = blockIdx.x * GEMM_B + threadIdx.x;
    int quad = tid >> 4;          // group of 4 nodes
    int g    = tid & 15;
    int node0 = quad * 4;
    if (node0 >= N_NODES) return;

    const float4* base = use_h ? g_h : (const float4*)in;

    unsigned long long acc01[4] = {0, 0, 0, 0};
    unsigned long long acc23[4] = {0, 0, 0, 0};

#pragma unroll
    for (int k4 = 0; k4 < 16; k4++) {
        float4 xv[4];
#pragma unroll
        for (int i = 0; i < 4; i++) xv[i] = base[(node0 + i) * 16 + k4];
#pragma unroll
        for (int s = 0; s < 4; s++) {
            float4 w = Ws[(k4 * 4 + s) * 16 + g];
            unsigned long long w01 = pk2(w.x, w.y);
            unsigned long long w23 = pk2(w.z, w.w);
#pragma unroll
            for (int i = 0; i < 4; i++) {
                float xk = (s == 0) ? xv[i].x : (s == 1) ? xv[i].y
                         : (s == 2) ? xv[i].z : xv[i].w;
                unsigned long long xx = pk2(xk, xk);
                fma2(acc01[i], w01, xx);
                fma2(acc23[i], w23, xx);
            }
        }
    }
#pragma unroll
    for (int i = 0; i < 4; i++) {
        float2 lo = upk2(acc01[i]);
        float2 hi = upk2(acc23[i]);
        g_t[(node0 + i) * 16 + g] = make_float4(lo.x, lo.y, hi.x, hi.y);
    }
}

// ---------------- fused aggregate: h = relu(csr_sum + selfloop + bias) ----
__global__ void agg_kernel(const float* __restrict__ bias) {
    int tid  = blockIdx.x * blockDim.x + threadIdx.x;
    int node = tid >> 4;
    int f    = tid & 15;
    if (node >= N_NODES) return;

    int beg = g_off[node];
    int end = g_off[node + 1];
    float di = g_dinv[node];
    float4 tv = g_t[node * 16 + f];
    float s = di * di;
    float4 acc = make_float4(tv.x * s, tv.y * s, tv.z * s, tv.w * s);

    int j = beg;
    for (; j + 3 < end; j += 4) {  // 4-deep for MLP
        int2 e0 = g_edge[j];
        int2 e1 = g_edge[j + 1];
        int2 e2 = g_edge[j + 2];
        int2 e3 = g_edge[j + 3];
        float4 v0 = g_t[e0.x * 16 + f];
        float4 v1 = g_t[e1.x * 16 + f];
        float4 v2 = g_t[e2.x * 16 + f];
        float4 v3 = g_t[e3.x * 16 + f];
        acc = f4fma(__int_as_float(e0.y), v0, acc);
        acc = f4fma(__int_as_float(e1.y), v1, acc);
        acc = f4fma(__int_as_float(e2.y), v2, acc);
        acc = f4fma(__int_as_float(e3.y), v3, acc);
    }
    for (; j < end; j++) {
        int2 e0 = g_edge[j];
        acc = f4fma(__int_as_float(e0.y), g_t[e0.x * 16 + f], acc);
    }

    float4 b = ((const float4*)bias)[f];
    float4 r;
    r.x = fmaxf(acc.x + b.x, 0.f);
    r.y = fmaxf(acc.y + b.y, 0.f);
    r.z = fmaxf(acc.z + b.z, 0.f);
    r.w = fmaxf(acc.w + b.w, 0.f);
    g_h[node * 16 + f] = r;
}

// ---------------- pooling ----------------
__global__ void pool_kernel(float* __restrict__ out) {
    __shared__ float4 sm[256];
    int g  = blockIdx.x;
    int t  = threadIdx.x;
    int f  = t & 15;
    int r0 = t >> 4;
    int beg = g_start[g];
    int end = g_start[g + 1];

    float4 acc = make_float4(0.f, 0.f, 0.f, 0.f);
    for (int r = beg + r0; r < end; r += 16) acc = f4add(acc, g_h[r * 16 + f]);
    sm[t] = acc;
    __syncthreads();
#pragma unroll
    for (int s = 8; s > 0; s >>= 1) {
        if (r0 < s) sm[t] = f4add(sm[t], sm[t + s * 16]);
        __syncthreads();
    }
    if (r0 == 0) {
        float inv = 1.0f / fmaxf((float)(end - beg), 1.0f);
        float4 v = sm[f];
        v.x *= inv; v.y *= inv; v.z *= inv; v.w *= inv;
        ((float4*)out)[g * 16 + f] = v;
    }
}

// ---------------- launch: bind inputs BY ELEMENT COUNT --------------------
extern "C" void kernel_launch(void* const* d_in, const int* in_sizes, int n_in,
                              void* d_out, int out_size) {
    const float* x     = 0;
    const int*   ei    = 0;
    const int*   batch = 0;
    const float* W[3] = {0, 0, 0};
    const float* B[3] = {0, 0, 0};
    int nw = 0, nb = 0;

    for (int i = 0; i < n_in; i++) {
        int sz = in_sizes[i];
        if      (sz == N_NODES * DH)  x     = (const float*)d_in[i];
        else if (sz == 2 * N_EDGES)   ei    = (const int*)d_in[i];
        else if (sz == N_NODES)       batch = (const int*)d_in[i];
        else if (sz == DH * DH) { if (nw < 3) W[nw++] = (const float*)d_in[i]; }
        else if (sz == DH)      { if (nb < 3) B[nb++] = (const float*)d_in[i]; }
    }
    if (!x || !ei || !batch || nw != 3 || nb != 3) return;

    float* out = (float*)d_out;

    const int TB = 256;
    const int gE    = (N_EDGES + TB - 1) / TB;        // 3125
    const int gN    = (N_NODES + TB - 1) / TB;        // 196
    const int gN16  = (N_NODES * 16 + TB - 1) / TB;   // 3125
    const int gQ    = (N_NODES / 4 * 16 + GEMM_B - 1) / GEMM_B;  // 782

    // ---- CSR build + norms (once) ----
    clear_kernel<<<gN, TB>>>();
    deg_kernel<<<gE, TB>>>(ei + N_EDGES);
    scan1_kernel<<<SCAN_NBLK, SCAN_B>>>();
    scan3_kernel<<<gN, TB>>>(batch);
    scatter_kernel<<<gE, TB>>>(ei);

    // ---- 3 GCN layers ----
    for (int l = 0; l < 3; l++) {
        gemm_kernel<<<gQ, GEMM_B>>>(x, W[l], l > 0);
        agg_kernel<<<gN16, TB>>>(B[l]);
    }

    // ---- global mean pool ----
    pool_kernel<<<NG, 256>>>(out);
}

// round 8
// speedup vs baseline: 1.9928x; 1.0564x over previous
#include <cuda_runtime.h>
#include <cuda_fp16.h>

#define N_NODES 50000
#define N_EDGES 800000
#define DH 64
#define NG 64

#define SCAN_B 512
#define SCAN_NBLK ((N_NODES + SCAN_B - 1) / SCAN_B)   // 98

// ---------------- device scratch ----------------
__device__ float  g_dinv[N_NODES];
__device__ int    g_degi[N_NODES];
__device__ int    g_off[N_NODES + 1];
__device__ int    g_cur[N_NODES];
__device__ int    g_bsum[SCAN_NBLK];
__device__ int2   g_edge[N_EDGES];
__device__ uint2  g_t16[N_NODES * 16];      // t in fp16 (4 halfs per uint2)
__device__ float4 g_h[N_NODES * 16];        // layer output (fp32)
__device__ int    g_start[NG + 1];

__device__ __forceinline__ float4 f4add(float4 a, float4 b) {
    return make_float4(a.x + b.x, a.y + b.y, a.z + b.z, a.w + b.w);
}

// packed f32x2 helpers (Blackwell dual-FP32 pipe; PTX-only)
__device__ __forceinline__ unsigned long long pk2(float a, float b) {
    unsigned long long r;
    asm("mov.b64 %0, {%1, %2};" : "=l"(r) : "f"(a), "f"(b));
    return r;
}
__device__ __forceinline__ void fma2(unsigned long long& d,
                                     unsigned long long a, unsigned long long b) {
    asm("fma.rn.f32x2 %0, %1, %2, %0;" : "+l"(d) : "l"(a), "l"(b));
}
__device__ __forceinline__ float2 upk2(unsigned long long v) {
    float2 f;
    asm("mov.b64 {%0, %1}, %2;" : "=f"(f.x), "=f"(f.y) : "l"(v));
    return f;
}

// unpack uint2 (4 fp16) -> 4 floats
__device__ __forceinline__ void upk_h4(uint2 u, float2& a, float2& b) {
    a = __half22float2(*(const __half2*)&u.x);
    b = __half22float2(*(const __half2*)&u.y);
}

// ---------------- prep ----------------
__global__ void clear_kernel() {
    int i = blockIdx.x * blockDim.x + threadIdx.x;
    if (i < N_NODES) g_degi[i] = 0;
}

__global__ void deg_kernel(const int* __restrict__ col) {
    int e = blockIdx.x * blockDim.x + threadIdx.x;
    if (e < N_EDGES) {
        int c = col[e];
        if (c >= 0 && c < N_NODES) atomicAdd(&g_degi[c], 1);
    }
}

// phase 1: per-block exclusive scan of degrees (+ fused dinv)
__global__ void scan1_kernel() {
    __shared__ int s[SCAN_B];
    int t = threadIdx.x;
    int i = blockIdx.x * SCAN_B + t;
    int v = (i < N_NODES) ? g_degi[i] : 0;
    if (i < N_NODES) g_dinv[i] = rsqrtf((float)v + 1.0f);
    s[t] = v;
    __syncthreads();
#pragma unroll
    for (int d = 1; d < SCAN_B; d <<= 1) {
        int u = (t >= d) ? s[t - d] : 0;
        __syncthreads();
        s[t] += u;
        __syncthreads();
    }
    if (i < N_NODES) g_off[i] = s[t] - v;
    if (t == SCAN_B - 1) g_bsum[blockIdx.x] = s[t];
}

// phase 2+3 fused (+ graph bounds)
__global__ void scan3_kernel(const int* __restrict__ batch) {
    __shared__ int s[128];
    int t = threadIdx.x;  // 256 threads
    if (t < 128) {
        int v = (t < SCAN_NBLK) ? g_bsum[t] : 0;
        s[t] = v;
    }
    __syncthreads();
#pragma unroll
    for (int d = 1; d < 128; d <<= 1) {
        int u = 0;
        if (t < 128 && t >= d) u = s[t - d];
        __syncthreads();
        if (t < 128) s[t] += u;
        __syncthreads();
    }
    int i = blockIdx.x * blockDim.x + t;
    if (i < N_NODES) {
        int blk = i / SCAN_B;
        int pre = s[blk] - g_bsum[blk];
        int off = g_off[i] + pre;
        g_off[i] = off;
        g_cur[i] = off;
        if (i == 0) g_off[N_NODES] = s[127];

        int b  = batch[i];
        int bp = (i == 0) ? -1 : batch[i - 1];
        if (b < 0) b = 0;
        if (b >= NG) b = NG - 1;
        if (bp < -1) bp = -1;
        if (bp >= NG) bp = NG - 1;
        for (int g = bp + 1; g <= b; g++) g_start[g] = i;
        if (i == N_NODES - 1)
            for (int g = b + 1; g <= NG; g++) g_start[g] = N_NODES;
    }
}

__global__ void scatter_kernel(const int* __restrict__ ei) {
    int e = blockIdx.x * blockDim.x + threadIdx.x;
    if (e >= N_EDGES) return;
    int r = ei[e];
    int c = ei[N_EDGES + e];
    if (r < 0 || r >= N_NODES || c < 0 || c >= N_NODES) return;
    int pos = atomicAdd(&g_cur[c], 1);
    float w = g_dinv[r] * g_dinv[c];
    g_edge[pos] = make_int2(r, __float_as_int(w));
}

// ---------------- GEMM: t16 = fp16(in @ W) ; 4 nodes/thread, f32x2 --------
#define GEMM_B 256
__global__ void gemm_kernel(const float* __restrict__ in,
                            const float* __restrict__ W, int use_h) {
    __shared__ float4 Ws[DH * 16];  // 16 KB
    const float4* W4 = (const float4*)W;
    for (int i = threadIdx.x; i < DH * 16; i += GEMM_B) Ws[i] = W4[i];
    __syncthreads();

    int tid  = blockIdx.x * GEMM_B + threadIdx.x;
    int quad = tid >> 4;
    int g    = tid & 15;
    int node0 = quad * 4;
    if (node0 >= N_NODES) return;

    const float4* base = use_h ? g_h : (const float4*)in;

    unsigned long long acc01[4] = {0, 0, 0, 0};
    unsigned long long acc23[4] = {0, 0, 0, 0};

#pragma unroll
    for (int k4 = 0; k4 < 16; k4++) {
        float4 xv[4];
#pragma unroll
        for (int i = 0; i < 4; i++) xv[i] = base[(node0 + i) * 16 + k4];
#pragma unroll
        for (int s = 0; s < 4; s++) {
            float4 w = Ws[(k4 * 4 + s) * 16 + g];
            unsigned long long w01 = pk2(w.x, w.y);
            unsigned long long w23 = pk2(w.z, w.w);
#pragma unroll
            for (int i = 0; i < 4; i++) {
                float xk = (s == 0) ? xv[i].x : (s == 1) ? xv[i].y
                         : (s == 2) ? xv[i].z : xv[i].w;
                unsigned long long xx = pk2(xk, xk);
                fma2(acc01[i], w01, xx);
                fma2(acc23[i], w23, xx);
            }
        }
    }
#pragma unroll
    for (int i = 0; i < 4; i++) {
        float2 lo = upk2(acc01[i]);
        float2 hi = upk2(acc23[i]);
        __half2 h01 = __floats2half2_rn(lo.x, lo.y);
        __half2 h23 = __floats2half2_rn(hi.x, hi.y);
        uint2 u;
        u.x = *(const unsigned int*)&h01;
        u.y = *(const unsigned int*)&h23;
        g_t16[(node0 + i) * 16 + g] = u;
    }
}

// ---------------- fused aggregate: h = relu(csr_sum + selfloop + bias) ----
__global__ void agg_kernel(const float* __restrict__ bias) {
    int tid  = blockIdx.x * blockDim.x + threadIdx.x;
    int node = tid >> 4;
    int f    = tid & 15;
    if (node >= N_NODES) return;

    int beg = g_off[node];
    int end = g_off[node + 1];
    float di = g_dinv[node];
    float s = di * di;

    float2 sa, sb;
    upk_h4(g_t16[node * 16 + f], sa, sb);
    float4 acc = make_float4(sa.x * s, sa.y * s, sb.x * s, sb.y * s);

    int j = beg;
    for (; j + 3 < end; j += 4) {  // 4-deep for MLP
        int2 e0 = g_edge[j];
        int2 e1 = g_edge[j + 1];
        int2 e2 = g_edge[j + 2];
        int2 e3 = g_edge[j + 3];
        uint2 u0 = g_t16[e0.x * 16 + f];
        uint2 u1 = g_t16[e1.x * 16 + f];
        uint2 u2 = g_t16[e2.x * 16 + f];
        uint2 u3 = g_t16[e3.x * 16 + f];
        float2 a, b;
        float w;
        w = __int_as_float(e0.y); upk_h4(u0, a, b);
        acc.x = fmaf(w, a.x, acc.x); acc.y = fmaf(w, a.y, acc.y);
        acc.z = fmaf(w, b.x, acc.z); acc.w = fmaf(w, b.y, acc.w);
        w = __int_as_float(e1.y); upk_h4(u1, a, b);
        acc.x = fmaf(w, a.x, acc.x); acc.y = fmaf(w, a.y, acc.y);
        acc.z = fmaf(w, b.x, acc.z); acc.w = fmaf(w, b.y, acc.w);
        w = __int_as_float(e2.y); upk_h4(u2, a, b);
        acc.x = fmaf(w, a.x, acc.x); acc.y = fmaf(w, a.y, acc.y);
        acc.z = fmaf(w, b.x, acc.z); acc.w = fmaf(w, b.y, acc.w);
        w = __int_as_float(e3.y); upk_h4(u3, a, b);
        acc.x = fmaf(w, a.x, acc.x); acc.y = fmaf(w, a.y, acc.y);
        acc.z = fmaf(w, b.x, acc.z); acc.w = fmaf(w, b.y, acc.w);
    }
    for (; j < end; j++) {
        int2 e0 = g_edge[j];
        float2 a, b;
        upk_h4(g_t16[e0.x * 16 + f], a, b);
        float w = __int_as_float(e0.y);
        acc.x = fmaf(w, a.x, acc.x); acc.y = fmaf(w, a.y, acc.y);
        acc.z = fmaf(w, b.x, acc.z); acc.w = fmaf(w, b.y, acc.w);
    }

    float4 b4 = ((const float4*)bias)[f];
    float4 r;
    r.x = fmaxf(acc.x + b4.x, 0.f);
    r.y = fmaxf(acc.y + b4.y, 0.f);
    r.z = fmaxf(acc.z + b4.z, 0.f);
    r.w = fmaxf(acc.w + b4.w, 0.f);
    g_h[node * 16 + f] = r;
}

// ---------------- pooling ----------------
__global__ void pool_kernel(float* __restrict__ out) {
    __shared__ float4 sm[256];
    int g  = blockIdx.x;
    int t  = threadIdx.x;
    int f  = t & 15;
    int r0 = t >> 4;
    int beg = g_start[g];
    int end = g_start[g + 1];

    float4 acc = make_float4(0.f, 0.f, 0.f, 0.f);
    for (int r = beg + r0; r < end; r += 16) acc = f4add(acc, g_h[r * 16 + f]);
    sm[t] = acc;
    __syncthreads();
#pragma unroll
    for (int s = 8; s > 0; s >>= 1) {
        if (r0 < s) sm[t] = f4add(sm[t], sm[t + s * 16]);
        __syncthreads();
    }
    if (r0 == 0) {
        float inv = 1.0f / fmaxf((float)(end - beg), 1.0f);
        float4 v = sm[f];
        v.x *= inv; v.y *= inv; v.z *= inv; v.w *= inv;
        ((float4*)out)[g * 16 + f] = v;
    }
}

// ---------------- launch: bind inputs BY ELEMENT COUNT --------------------
extern "C" void kernel_launch(void* const* d_in, const int* in_sizes, int n_in,
                              void* d_out, int out_size) {
    const float* x     = 0;
    const int*   ei    = 0;
    const int*   batch = 0;
    const float* W[3] = {0, 0, 0};
    const float* B[3] = {0, 0, 0};
    int nw = 0, nb = 0;

    for (int i = 0; i < n_in; i++) {
        int sz = in_sizes[i];
        if      (sz == N_NODES * DH)  x     = (const float*)d_in[i];
        else if (sz == 2 * N_EDGES)   ei    = (const int*)d_in[i];
        else if (sz == N_NODES)       batch = (const int*)d_in[i];
        else if (sz == DH * DH) { if (nw < 3) W[nw++] = (const float*)d_in[i]; }
        else if (sz == DH)      { if (nb < 3) B[nb++] = (const float*)d_in[i]; }
    }
    if (!x || !ei || !batch || nw != 3 || nb != 3) return;

    float* out = (float*)d_out;

    const int TB = 256;
    const int gE    = (N_EDGES + TB - 1) / TB;        // 3125
    const int gN    = (N_NODES + TB - 1) / TB;        // 196
    const int gN16  = (N_NODES * 16 + TB - 1) / TB;   // 3125
    const int gQ    = (N_NODES / 4 * 16 + GEMM_B - 1) / GEMM_B;  // 782

    // ---- CSR build + norms (once) ----
    clear_kernel<<<gN, TB>>>();
    deg_kernel<<<gE, TB>>>(ei + N_EDGES);
    scan1_kernel<<<SCAN_NBLK, SCAN_B>>>();
    scan3_kernel<<<gN, TB>>>(batch);
    scatter_kernel<<<gE, TB>>>(ei);

    // ---- 3 GCN layers ----
    for (int l = 0; l < 3; l++) {
        gemm_kernel<<<gQ, GEMM_B>>>(x, W[l], l > 0);
        agg_kernel<<<gN16, TB>>>(B[l]);
    }

    // ---- global mean pool ----
    pool_kernel<<<NG, 256>>>(out);
}